// round 11
// baseline (speedup 1.0000x reference)
#include <cuda_runtime.h>

// Problem constants (fixed shapes from reference)
#define B_    64
#define G_    128
#define A_    3
#define N_    1280
#define CH_   (A_ * 5)             // 15 floats per (b,gy,gx) cell
#define TOT_  (B_ * G_ * G_ * CH_) // 15,728,640 floats
#define TOT4_ (TOT_ / 4)           // 3,932,160 float4

#define BLOCK_  320                // multiple of 5: i%5 per-thread constant for ANY grid
#define GRID_   888                // 148 SMs * 6 blocks = 1920 thr/SM (93.75% occ)
#define STRIDE_ (GRID_ * BLOCK_)   // 284,160  (== 0 mod 5 and mod 4)

// Scratch for single-kernel two-phase reduction (allowed: __device__ globals).
__device__ float        g_partials[GRID_];
__device__ unsigned int g_done = 0;   // self-resetting via atomicInc wrap

__device__ __forceinline__ float softplus_fast(float v) {
    // log(1+exp(v)) = max(v,0) + log(1+exp(-|v|)); fast intrinsics (2 MUFU).
    float a = fabsf(v);
    return fmaxf(v, 0.0f) + __logf(1.0f + __expf(-a));
}

// float4 i holds a conf value at component (i mod 5); none when i%5==4.
__device__ __forceinline__ float pick(float4 v, int comp) {
    return (comp == 0) ? v.x : (comp == 1) ? v.y : (comp == 2) ? v.z : v.w;
}

// Block reduce; returns full block sum on thread 0 (garbage elsewhere).
__device__ __forceinline__ float block_reduce(float s) {
    #pragma unroll
    for (int o = 16; o > 0; o >>= 1)
        s += __shfl_down_sync(0xFFFFFFFFu, s, o);
    __shared__ float sm[BLOCK_ / 32];
    int lane = threadIdx.x & 31;
    int wid  = threadIdx.x >> 5;
    if (lane == 0) sm[wid] = s;
    __syncthreads();
    if (wid == 0) {
        s = (lane < (BLOCK_ / 32)) ? sm[lane] : 0.0f;
        #pragma unroll
        for (int o = 16; o > 0; o >>= 1)
            s += __shfl_down_sync(0xFFFFFFFFu, s, o);
    }
    return s;
}

__global__ void __launch_bounds__(BLOCK_, 6)
yolo_loss_kernel(const float* __restrict__ yp,
                 const float* __restrict__ boxes,
                 const float* __restrict__ anchors,
                 const int*   __restrict__ bidx,
                 float* __restrict__ out) {
    const int tid  = threadIdx.x;
    const int gidx = blockIdx.x * BLOCK_ + tid;

    // ---- Sparse pass (first 4 blocks; 1280 boxes) -------------------------
    float s_box = 0.0f;
    if (gidx < N_) {
        const float inv_stride = 1.0f / 8.0f;  // stride = 1024/128 = 8
        float gx = boxes[gidx * 4 + 0] * inv_stride;
        float gy = boxes[gidx * 4 + 1] * inv_stride;
        float gw = boxes[gidx * 4 + 2] * inv_stride;
        float gh = boxes[gidx * 4 + 3] * inv_stride;
        int gi = (int)gx;
        int gj = (int)gy;

        // argmax IoU over 3 anchors (ties -> first index, matching jnp.argmax)
        int   best  = 0;
        float bestv = -1.0f, baw = 0.0f, bah = 0.0f;
        #pragma unroll
        for (int a = 0; a < A_; a++) {
            float aw = anchors[2 * a + 0] * inv_stride;
            float ah = anchors[2 * a + 1] * inv_stride;
            float inter = fminf(aw, gw) * fminf(ah, gh);
            float uni   = aw * ah + gw * gh - inter;
            float iou   = inter / uni;
            if (iou > bestv) { bestv = iou; best = a; baw = aw; bah = ah; }
        }

        float tx = gx - (float)gi;
        float ty = gy - (float)gj;
        float tw = __logf(gw / baw);
        float th = __logf(gh / bah);

        int b = bidx[gidx];
        const float* p = yp + ((size_t)((b * G_ + gj) * G_ + gi)) * CH_ + best * 5;
        float conf = p[0];
        float x = 1.0f / (1.0f + __expf(-p[1]));
        float y = 1.0f / (1.0f + __expf(-p[2]));
        float w = p[3];
        float h = p[4];

        float dx = x - tx, dy = y - ty, dw = w - tw, dh = h - th;
        s_box = -0.5f /*NOOBJ*/ * softplus_fast(conf)
              +  1.0f /*OBJ*/   * softplus_fast(-conf)
              +  5.0f /*COORD*/ * (dx * dx + dy * dy + dw * dw + dh * dh);
    }

    // ---- Dense pass: pure aligned stream over ALL float4s -----------------
    // Warp requests are dense, 128B-aligned spans (no holes). STRIDE_ % 5 == 0
    // => comp = i%5 is per-thread constant; float4s with comp==4 carry no conf
    // and are masked out after the loop. __ldcs: zero-reuse stream, evict-first.
    const int   comp = gidx % 5;
    const float mask = (comp < 4) ? 1.0f : 0.0f;

    float s0 = 0.0f, s1 = 0.0f, s2 = 0.0f, s3 = 0.0f;
    const float4* p  = reinterpret_cast<const float4*>(yp) + gidx;
    const float4* pe = reinterpret_cast<const float4*>(yp) + TOT4_;

    // 4 independent LDG.128 per batch; base-pointer + small-index addressing
    // keeps register count inside the 34-reg/6-block budget.
    while (p + 3 * STRIDE_ < pe) {
        float4 v0 = __ldcs(p);
        float4 v1 = __ldcs(p +     STRIDE_);
        float4 v2 = __ldcs(p + 2 * STRIDE_);
        float4 v3 = __ldcs(p + 3 * STRIDE_);
        p += 4 * STRIDE_;
        s0 += softplus_fast(pick(v0, comp));
        s1 += softplus_fast(pick(v1, comp));
        s2 += softplus_fast(pick(v2, comp));
        s3 += softplus_fast(pick(v3, comp));
    }
    while (p < pe) {
        s0 += softplus_fast(pick(__ldcs(p), comp));
        p += STRIDE_;
    }

    float s_dense = mask * ((s0 + s1) + (s2 + s3));

    // ---- Two-phase reduction in one kernel --------------------------------
    float bsum = block_reduce(0.5f /*NOOBJ*/ * s_dense + s_box);

    __shared__ bool is_last;
    if (tid == 0) {
        g_partials[blockIdx.x] = bsum;
        __threadfence();
        // atomicInc wraps to 0 at GRID_-1 -> counter self-resets each launch.
        unsigned prev = atomicInc(&g_done, GRID_ - 1);
        is_last = (prev == GRID_ - 1);
    }
    __syncthreads();

    if (is_last) {
        __threadfence();  // make all partials visible to this block
        float s = 0.0f;
        for (int k = tid; k < GRID_; k += BLOCK_)
            s += g_partials[k];
        float total = block_reduce(s);
        if (tid == 0) out[0] = total;
    }
}

extern "C" void kernel_launch(void* const* d_in, const int* in_sizes, int n_in,
                              void* d_out, int out_size) {
    const float* y_pred  = (const float*)d_in[0];
    const float* boxes   = (const float*)d_in[1];
    const float* anchors = (const float*)d_in[2];
    const int*   bidx    = (const int*)d_in[3];
    float* out = (float*)d_out;

    yolo_loss_kernel<<<GRID_, BLOCK_>>>(y_pred, boxes, anchors, bidx, out);
}

// round 12
// speedup vs baseline: 1.0311x; 1.0311x over previous
#include <cuda_runtime.h>

// Problem constants (fixed shapes from reference)
#define B_    64
#define G_    128
#define A_    3
#define N_    1280
#define CH_   (A_ * 5)             // 15 floats per (b,gy,gx) cell
#define TOT_  (B_ * G_ * G_ * CH_) // 15,728,640 floats
#define TOT4_ (TOT_ / 4)           // 3,932,160 float4

#define GRID_   885                // 5*177; <= 148 SMs * 6 resident: ONE wave
#define BLOCK_  256
#define STRIDE_ (GRID_ * BLOCK_)   // 226,560  (== 0 mod 5  AND  mod 4)

// Scratch for single-kernel two-phase reduction (allowed: __device__ globals).
__device__ float        g_partials[GRID_];
__device__ unsigned int g_done = 0;   // self-resetting via atomicInc wrap

__device__ __forceinline__ float softplus_fast(float v) {
    // log(1+exp(v)) = max(v,0) + log(1+exp(-|v|)); fast intrinsics (2 MUFU).
    float a = fabsf(v);
    return fmaxf(v, 0.0f) + __logf(1.0f + __expf(-a));
}

// float4 i holds a conf value at component (i mod 5); none when i%5==4.
__device__ __forceinline__ float pick(float4 v, int comp) {
    return (comp == 0) ? v.x : (comp == 1) ? v.y : (comp == 2) ? v.z : v.w;
}

// Block reduce; returns full block sum on thread 0 (garbage elsewhere).
__device__ __forceinline__ float block_reduce(float s) {
    #pragma unroll
    for (int o = 16; o > 0; o >>= 1)
        s += __shfl_down_sync(0xFFFFFFFFu, s, o);
    __shared__ float sm[BLOCK_ / 32];
    int lane = threadIdx.x & 31;
    int wid  = threadIdx.x >> 5;
    if (lane == 0) sm[wid] = s;
    __syncthreads();
    if (wid == 0) {
        s = (lane < (BLOCK_ / 32)) ? sm[lane] : 0.0f;
        #pragma unroll
        for (int o = 16; o > 0; o >>= 1)
            s += __shfl_down_sync(0xFFFFFFFFu, s, o);
    }
    return s;
}

__global__ void __launch_bounds__(BLOCK_, 6)
yolo_loss_kernel(const float* __restrict__ yp,
                 const float* __restrict__ boxes,
                 const float* __restrict__ anchors,
                 const int*   __restrict__ bidx,
                 float* __restrict__ out) {
    const int tid  = threadIdx.x;
    const int gidx = blockIdx.x * BLOCK_ + tid;

    // ---- Sparse pass (first 5 blocks; 1280 boxes) -------------------------
    float s_box = 0.0f;
    if (gidx < N_) {
        const float inv_stride = 1.0f / 8.0f;  // stride = 1024/128 = 8
        float gx = boxes[gidx * 4 + 0] * inv_stride;
        float gy = boxes[gidx * 4 + 1] * inv_stride;
        float gw = boxes[gidx * 4 + 2] * inv_stride;
        float gh = boxes[gidx * 4 + 3] * inv_stride;
        int gi = (int)gx;
        int gj = (int)gy;

        // argmax IoU over 3 anchors (ties -> first index, matching jnp.argmax)
        int   best  = 0;
        float bestv = -1.0f, baw = 0.0f, bah = 0.0f;
        #pragma unroll
        for (int a = 0; a < A_; a++) {
            float aw = anchors[2 * a + 0] * inv_stride;
            float ah = anchors[2 * a + 1] * inv_stride;
            float inter = fminf(aw, gw) * fminf(ah, gh);
            float uni   = aw * ah + gw * gh - inter;
            float iou   = inter / uni;
            if (iou > bestv) { bestv = iou; best = a; baw = aw; bah = ah; }
        }

        float tx = gx - (float)gi;
        float ty = gy - (float)gj;
        float tw = __logf(gw / baw);
        float th = __logf(gh / bah);

        int b = bidx[gidx];
        const float* p = yp + ((size_t)((b * G_ + gj) * G_ + gi)) * CH_ + best * 5;
        float conf = p[0];
        float x = 1.0f / (1.0f + __expf(-p[1]));
        float y = 1.0f / (1.0f + __expf(-p[2]));
        float w = p[3];
        float h = p[4];

        float dx = x - tx, dy = y - ty, dw = w - tw, dh = h - th;
        s_box = -0.5f /*NOOBJ*/ * softplus_fast(conf)
              +  1.0f /*OBJ*/   * softplus_fast(-conf)
              +  5.0f /*COORD*/ * (dx * dx + dy * dy + dw * dw + dh * dh);
    }

    // ---- Dense pass: pure aligned stream over ALL float4s -----------------
    // Warp requests are dense, 128B-aligned 512B spans (4 lines, no holes).
    // STRIDE_ % 5 == 0  =>  i % 5 is per-thread constant => comp & mask are
    // loop-invariant; float4s with i%5==4 carry no conf and are masked out.
    const int   comp = gidx % 5;
    const float mask = (comp < 4) ? 1.0f : 0.0f;
    const float4* yp4 = reinterpret_cast<const float4*>(yp);

    float s0 = 0.0f, s1 = 0.0f, s2 = 0.0f, s3 = 0.0f;
    int i = gidx;
    // 4 independent LDG.128 per batch (16 data regs; fits the 42-reg budget).
    for (; i + 3 * STRIDE_ < TOT4_; i += 4 * STRIDE_) {
        float4 v0 = yp4[i];
        float4 v1 = yp4[i +     STRIDE_];
        float4 v2 = yp4[i + 2 * STRIDE_];
        float4 v3 = yp4[i + 3 * STRIDE_];
        s0 += softplus_fast(pick(v0, comp));
        s1 += softplus_fast(pick(v1, comp));
        s2 += softplus_fast(pick(v2, comp));
        s3 += softplus_fast(pick(v3, comp));
    }
    for (; i < TOT4_; i += STRIDE_)
        s0 += softplus_fast(pick(yp4[i], comp));

    float s_dense = mask * ((s0 + s1) + (s2 + s3));

    // ---- Two-phase reduction in one kernel --------------------------------
    float bsum = block_reduce(0.5f /*NOOBJ*/ * s_dense + s_box);

    __shared__ bool is_last;
    if (tid == 0) {
        g_partials[blockIdx.x] = bsum;
        __threadfence();
        // atomicInc wraps to 0 at GRID_-1 -> counter self-resets each launch.
        unsigned prev = atomicInc(&g_done, GRID_ - 1);
        is_last = (prev == GRID_ - 1);
    }
    __syncthreads();

    if (is_last) {
        __threadfence();  // make all partials visible to this block
        float s = 0.0f;
        for (int k = tid; k < GRID_; k += BLOCK_)
            s += g_partials[k];
        float total = block_reduce(s);
        if (tid == 0) out[0] = total;
    }
}

extern "C" void kernel_launch(void* const* d_in, const int* in_sizes, int n_in,
                              void* d_out, int out_size) {
    const float* y_pred  = (const float*)d_in[0];
    const float* boxes   = (const float*)d_in[1];
    const float* anchors = (const float*)d_in[2];
    const int*   bidx    = (const int*)d_in[3];
    float* out = (float*)d_out;

    yolo_loss_kernel<<<GRID_, BLOCK_>>>(y_pred, boxes, anchors, bidx, out);
}

// round 13
// speedup vs baseline: 1.1629x; 1.1278x over previous
#include <cuda_runtime.h>

// Problem constants (fixed shapes from reference)
#define B_    64
#define G_    128
#define A_    3
#define N_    1280
#define CH_   (A_ * 5)             // 15 floats per (b,gy,gx) cell
#define TOT_  (B_ * G_ * G_ * CH_) // 15,728,640 floats
#define TOT4_ (TOT_ / 4)           // 3,932,160 float4

#define GRID_   740                // 148 SMs * 5 resident blocks: ONE uniform wave
#define BLOCK_  256
#define STRIDE_ (GRID_ * BLOCK_)   // 189,440  (== 0 mod 5  AND  mod 4)

// Scratch for single-kernel reduction (allowed: __device__ globals).
// g_sum / g_done are self-resetting each launch (atomicExch / atomicInc wrap),
// so the kernel is graph-replay deterministic.
__device__ float        g_sum  = 0.0f;
__device__ unsigned int g_done = 0;

__device__ __forceinline__ float softplus_fast(float v) {
    // log(1+exp(v)) = max(v,0) + log(1+exp(-|v|)); fast intrinsics (2 MUFU).
    float a = fabsf(v);
    return fmaxf(v, 0.0f) + __logf(1.0f + __expf(-a));
}

// float4 i holds a conf value at component (i mod 5); none when i%5==4.
__device__ __forceinline__ float pick(float4 v, int comp) {
    return (comp == 0) ? v.x : (comp == 1) ? v.y : (comp == 2) ? v.z : v.w;
}

// Block reduce; returns full block sum on thread 0 (garbage elsewhere).
__device__ __forceinline__ float block_reduce(float s) {
    #pragma unroll
    for (int o = 16; o > 0; o >>= 1)
        s += __shfl_down_sync(0xFFFFFFFFu, s, o);
    __shared__ float sm[BLOCK_ / 32];
    int lane = threadIdx.x & 31;
    int wid  = threadIdx.x >> 5;
    if (lane == 0) sm[wid] = s;
    __syncthreads();
    if (wid == 0) {
        s = (lane < (BLOCK_ / 32)) ? sm[lane] : 0.0f;
        #pragma unroll
        for (int o = 16; o > 0; o >>= 1)
            s += __shfl_down_sync(0xFFFFFFFFu, s, o);
    }
    return s;
}

__global__ void __launch_bounds__(BLOCK_, 5)
yolo_loss_kernel(const float* __restrict__ yp,
                 const float* __restrict__ boxes,
                 const float* __restrict__ anchors,
                 const int*   __restrict__ bidx,
                 float* __restrict__ out) {
    const int tid  = threadIdx.x;
    const int gidx = blockIdx.x * BLOCK_ + tid;

    // ---- Sparse pass (first 5 blocks; 1280 boxes) -------------------------
    float s_box = 0.0f;
    if (gidx < N_) {
        const float inv_stride = 1.0f / 8.0f;  // stride = 1024/128 = 8
        float gx = boxes[gidx * 4 + 0] * inv_stride;
        float gy = boxes[gidx * 4 + 1] * inv_stride;
        float gw = boxes[gidx * 4 + 2] * inv_stride;
        float gh = boxes[gidx * 4 + 3] * inv_stride;
        int gi = (int)gx;
        int gj = (int)gy;

        // argmax IoU over 3 anchors (ties -> first index, matching jnp.argmax)
        int   best  = 0;
        float bestv = -1.0f, baw = 0.0f, bah = 0.0f;
        #pragma unroll
        for (int a = 0; a < A_; a++) {
            float aw = anchors[2 * a + 0] * inv_stride;
            float ah = anchors[2 * a + 1] * inv_stride;
            float inter = fminf(aw, gw) * fminf(ah, gh);
            float uni   = aw * ah + gw * gh - inter;
            float iou   = inter / uni;
            if (iou > bestv) { bestv = iou; best = a; baw = aw; bah = ah; }
        }

        float tx = gx - (float)gi;
        float ty = gy - (float)gj;
        float tw = __logf(gw / baw);
        float th = __logf(gh / bah);

        int b = bidx[gidx];
        const float* p = yp + ((size_t)((b * G_ + gj) * G_ + gi)) * CH_ + best * 5;
        float conf = p[0];
        float x = 1.0f / (1.0f + __expf(-p[1]));
        float y = 1.0f / (1.0f + __expf(-p[2]));
        float w = p[3];
        float h = p[4];

        float dx = x - tx, dy = y - ty, dw = w - tw, dh = h - th;
        s_box = -0.5f /*NOOBJ*/ * softplus_fast(conf)
              +  1.0f /*OBJ*/   * softplus_fast(-conf)
              +  5.0f /*COORD*/ * (dx * dx + dy * dy + dw * dw + dh * dh);
    }

    // ---- Dense pass: pure aligned stream over ALL float4s -----------------
    // Warp requests are dense, 128B-aligned 512B spans (4 lines, no holes).
    // STRIDE_ % 5 == 0  =>  i % 5 is per-thread constant => comp & mask are
    // loop-invariant; float4s with i%5==4 carry no conf and are masked out.
    const int   comp = gidx % 5;
    const float mask = (comp < 4) ? 1.0f : 0.0f;
    const float4* yp4 = reinterpret_cast<const float4*>(yp);

    float s0 = 0.0f, s1 = 0.0f, s2 = 0.0f, s3 = 0.0f;
    int i = gidx;
    // 4 independent LDG.128 per batch (16 data regs; fits the reg budget).
    for (; i + 3 * STRIDE_ < TOT4_; i += 4 * STRIDE_) {
        float4 v0 = yp4[i];
        float4 v1 = yp4[i +     STRIDE_];
        float4 v2 = yp4[i + 2 * STRIDE_];
        float4 v3 = yp4[i + 3 * STRIDE_];
        s0 += softplus_fast(pick(v0, comp));
        s1 += softplus_fast(pick(v1, comp));
        s2 += softplus_fast(pick(v2, comp));
        s3 += softplus_fast(pick(v3, comp));
    }
    for (; i < TOT4_; i += STRIDE_)
        s0 += softplus_fast(pick(yp4[i], comp));

    float s_dense = mask * ((s0 + s1) + (s2 + s3));

    // ---- Final reduction: one global atomic per block ---------------------
    float bsum = block_reduce(0.5f /*NOOBJ*/ * s_dense + s_box);

    if (tid == 0) {
        atomicAdd(&g_sum, bsum);
        __threadfence();
        // atomicInc wraps to 0 at GRID_-1 -> counter self-resets each launch.
        unsigned prev = atomicInc(&g_done, GRID_ - 1);
        if (prev == GRID_ - 1) {
            // Last arrival: every block's add precedes its inc (fenced), so
            // g_sum is complete. Exchange fetches the total AND resets the
            // accumulator for the next graph replay.
            float total = atomicExch(&g_sum, 0.0f);
            out[0] = total;
        }
    }
}

extern "C" void kernel_launch(void* const* d_in, const int* in_sizes, int n_in,
                              void* d_out, int out_size) {
    const float* y_pred  = (const float*)d_in[0];
    const float* boxes   = (const float*)d_in[1];
    const float* anchors = (const float*)d_in[2];
    const int*   bidx    = (const int*)d_in[3];
    float* out = (float*)d_out;

    yolo_loss_kernel<<<GRID_, BLOCK_>>>(y_pred, boxes, anchors, bidx, out);
}